// round 4
// baseline (speedup 1.0000x reference)
#include <cuda_runtime.h>
#include <math_constants.h>

// Chamfer distance: B=8, N=M=4096, D=2 on sm_100a — single fused kernel.
// Work item = (dbsplit, pair, qtile): 4 x 16 x 4 = 256 blocks of 256 threads.
// Each thread handles Q=4 queries against a 1024-point DB chunk staged in smem
// as packed pairs (u0,u1) = -2*t and h = |t|^2; score via fma.rn.f32x2.
// Per-query clamped partial d^2 goes to g_pmin[pair][qi][split] (float4 row).
// The last-arriving block of each pair finalizes: min over splits, sqrt, sum,
// one atomicAdd into d_out. Counters self-reset for graph replay.

#define NPTS    4096
#define THREADS 256
#define Q       4
#define DBSPLIT 4
#define DBCHUNK (NPTS / DBSPLIT)                 // 1024 points
#define QTILES  (NPTS / (THREADS * Q))           // 4
#define NPAIRS  16

__device__ float g_pmin[NPAIRS * NPTS * DBSPLIT];  // [pair][qi][split], 1 MB
__device__ int   g_count[NPAIRS];                   // zero-init; self-reset

union F2 { unsigned long long u; float2 f; };

__device__ __forceinline__ unsigned long long ffma2(unsigned long long a,
                                                    unsigned long long b,
                                                    unsigned long long c)
{
    unsigned long long d;
    asm("fma.rn.f32x2 %0, %1, %2, %3;" : "=l"(d) : "l"(a), "l"(b), "l"(c));
    return d;
}

__device__ __forceinline__ unsigned long long bcast2(float v)
{
    unsigned long long r;
    asm("mov.b64 %0, {%1, %1};" : "=l"(r) : "f"(v));
    return r;
}

__global__ __launch_bounds__(THREADS)
void chamfer_fused(const float* __restrict__ x, const float* __restrict__ tgt,
                   float* __restrict__ out)
{
    __shared__ __align__(16) float4 s_uv[DBCHUNK / 2];   // 8 KB: (u0a,u0b,u1a,u1b)
    __shared__ __align__(16) float2 s_h[DBCHUNK / 2];    // 4 KB: (ha,hb)
    __shared__ float s_warp[THREADS / 32];
    __shared__ int   s_last;

    const int blk   = blockIdx.x;
    const int qtile = blk & (QTILES - 1);
    const int pair  = (blk >> 2) & (NPAIRS - 1);
    const int split = blk >> 6;
    const int dir   = pair & 1;
    const int b     = pair >> 1;

    const float* q_base = (dir ? tgt : x) + (size_t)b * NPTS * 2;
    const float* d_base = (dir ? x : tgt) + (size_t)b * NPTS * 2
                          + (size_t)split * DBCHUNK * 2;

    // Stage DB chunk (512 point-pairs, 2 per thread).
    const float4* db4 = (const float4*)d_base;
    #pragma unroll
    for (int p = threadIdx.x; p < DBCHUNK / 2; p += THREADS) {
        float4 t = db4[p];                  // (t0x,t0y,t1x,t1y)
        s_uv[p] = make_float4(-2.0f * t.x, -2.0f * t.z,
                              -2.0f * t.y, -2.0f * t.w);
        s_h[p]  = make_float2(fmaf(t.x, t.x, t.y * t.y),
                              fmaf(t.z, t.z, t.w * t.w));
    }
    __syncthreads();

    // Q=4 queries per thread.
    int qi[Q];
    unsigned long long qxx[Q], qyy[Q];
    float q2[Q];
    #pragma unroll
    for (int k = 0; k < Q; k++) {
        qi[k] = qtile * (THREADS * Q) + k * THREADS + threadIdx.x;
        float2 q = ((const float2*)q_base)[qi[k]];
        qxx[k] = bcast2(q.x);
        qyy[k] = bcast2(q.y);
        q2[k]  = fmaf(q.x, q.x, q.y * q.y);
    }

    float mA[Q], mB[Q];
    #pragma unroll
    for (int k = 0; k < Q; k++) { mA[k] = CUDART_INF_F; mB[k] = CUDART_INF_F; }

    const ulonglong2* uvp = (const ulonglong2*)s_uv;  // [p]: (u0pk, u1pk)
    const ulonglong2* hpp = (const ulonglong2*)s_h;   // [i]: h of pts 4i..4i+3

    #pragma unroll 4
    for (int i = 0; i < DBCHUNK / 4; i++) {           // 4 points per iter
        ulonglong2 uvA = uvp[2 * i];
        ulonglong2 uvB = uvp[2 * i + 1];
        ulonglong2 hh  = hpp[i];
        #pragma unroll
        for (int k = 0; k < Q; k++) {
            F2 sA, sB;
            sA.u = ffma2(qxx[k], uvA.x, ffma2(qyy[k], uvA.y, hh.x));
            sB.u = ffma2(qxx[k], uvB.x, ffma2(qyy[k], uvB.y, hh.y));
            mA[k] = fminf(mA[k], sA.f.x);
            mB[k] = fminf(mB[k], sA.f.y);
            mA[k] = fminf(mA[k], sB.f.x);
            mB[k] = fminf(mB[k], sB.f.y);
        }
    }

    // Store clamped partial d^2 (clamp commutes with min across splits).
    #pragma unroll
    for (int k = 0; k < Q; k++) {
        float d2 = fmaxf(fminf(mA[k], mB[k]) + q2[k], 0.0f);
        g_pmin[((size_t)pair * NPTS + qi[k]) * DBSPLIT + split] = d2;
    }

    // Arrival protocol.
    __threadfence();
    __syncthreads();
    if (threadIdx.x == 0)
        s_last = (atomicAdd(&g_count[pair], 1) == DBSPLIT * QTILES - 1);
    __syncthreads();
    if (!s_last) return;

    // Last block of this pair: combine splits, sqrt, sum.
    __threadfence();
    const float4* pm4 = (const float4*)(g_pmin + (size_t)pair * NPTS * DBSPLIT);
    float acc = 0.0f;
    #pragma unroll
    for (int q = threadIdx.x; q < NPTS; q += THREADS) {
        float4 p = pm4[q];
        float m = fminf(fminf(p.x, p.y), fminf(p.z, p.w));
        acc += sqrtf(m);
    }

    #pragma unroll
    for (int off = 16; off > 0; off >>= 1)
        acc += __shfl_down_sync(0xFFFFFFFFu, acc, off);
    const int lane = threadIdx.x & 31;
    const int wid  = threadIdx.x >> 5;
    if (lane == 0) s_warp[wid] = acc;
    __syncthreads();
    if (wid == 0) {
        float w = (lane < THREADS / 32) ? s_warp[lane] : 0.0f;
        #pragma unroll
        for (int off = 4; off > 0; off >>= 1)
            w += __shfl_down_sync(0xFFFFFFFFu, w, off);
        if (lane == 0) {
            atomicAdd(out, w * (1.0f / 32768.0f));
            g_count[pair] = 0;               // reset for next graph replay
        }
    }
}

extern "C" void kernel_launch(void* const* d_in, const int* in_sizes, int n_in,
                              void* d_out, int out_size)
{
    const float* x   = (const float*)d_in[0];   // [8,4096,2] f32
    const float* tgt = (const float*)d_in[1];   // [8,4096,2] f32
    float* out = (float*)d_out;

    (void)in_sizes; (void)n_in; (void)out_size;

    cudaMemsetAsync(d_out, 0, sizeof(float));
    chamfer_fused<<<DBSPLIT * NPAIRS * QTILES, THREADS>>>(x, tgt, out);
}